// round 15
// baseline (speedup 1.0000x reference)
#include <cuda_runtime.h>
#include <cstdint>

// Problem constants
#define NN   512
#define NIN  6
#define NOUT 2
#define TS   1200
#define NB   128
#define TB   (TS * NB)          // 153600

// Decomposition: 16 cluster-groups x (cluster of 8 n-slice CTAs) = 128 CTAs.
// Each cluster interleaves TWO independent 4-batch chains (A/B): each chain's
// DSMEM exchange latency hides under the other's compute.
#define NSL     8               // n-slices (cluster size)
#define ROWS    64              // rows of W_rec per CTA
#define NCH     2               // chains per cluster
#define BG      4               // batch per group (32 groups total)
#define THREADS 256
#define NSEG    16              // k-segments (8 warps x 2 half-warps)
#define BP      12              // partials row pad: n*12+b covers all 32 banks

#define F_BUF   ((NN + NIN + 2) * BG)   // 2080 floats per state buffer
#define BUF_BYTES (F_BUF * 4)           // 8320
#define F_PART  (NSEG * ROWS * BP)      // 12288
#define SLICE   (ROWS * BG)             // 256 floats
#define SLICE_BYTES (SLICE * 4)         // 1024
#define F_STG   (NCH * 2 * SLICE)       // 1024
#define F_MBAR  8                       // 4 x 8-byte mbarriers
#define SMEM_FLOATS (NCH * 2 * F_BUF + F_PART + F_STG + F_MBAR)
#define SMEM_BYTES  (SMEM_FLOATS * 4)   // 86,560 B

// tx bytes per chain-phase: 8 bulk copies x 1024 B + 24 x 4 B (x rows)
#define TXB (NSL * SLICE_BYTES + NIN * BG * 4)   // 8288

typedef unsigned long long ull;

__device__ __forceinline__ ull pack2(float x) {
    ull r;
    unsigned int v = __float_as_uint(x);
    asm("mov.b64 %0, {%1, %1};" : "=l"(r) : "r"(v));
    return r;
}
__device__ __forceinline__ void fma2(ull& d, ull a, ull b) {
    asm("fma.rn.f32x2 %0, %1, %2, %0;" : "+l"(d) : "l"(a), "l"(b));
}
__device__ __forceinline__ void unpack2(ull v, float& lo, float& hi) {
    unsigned int l, h;
    asm("mov.b64 {%0, %1}, %2;" : "=r"(l), "=r"(h) : "l"(v));
    lo = __uint_as_float(l);
    hi = __uint_as_float(h);
}
__device__ __forceinline__ float tanh_fast(float x) {
    float r;
    asm("tanh.approx.f32 %0, %1;" : "=f"(r) : "f"(x));
    return r;
}
__device__ __forceinline__ uint32_t smem_u32(const void* p) {
    uint32_t a;
    asm("{ .reg .u64 t; cvta.to.shared.u64 t, %1; cvt.u32.u64 %0, t; }"
        : "=r"(a) : "l"(p));
    return a;
}
__device__ __forceinline__ uint32_t mapa_rank(uint32_t addr, uint32_t rank) {
    uint32_t r;
    asm("mapa.shared::cluster.u32 %0, %1, %2;" : "=r"(r) : "r"(addr), "r"(rank));
    return r;
}
__device__ __forceinline__ void mbar_init(uint32_t addr, uint32_t cnt) {
    asm volatile("mbarrier.init.shared.b64 [%0], %1;" :: "r"(addr), "r"(cnt) : "memory");
}
__device__ __forceinline__ void mbar_expect_tx(uint32_t addr, uint32_t bytes) {
    asm volatile("mbarrier.arrive.expect_tx.shared.b64 _, [%0], %1;"
                 :: "r"(addr), "r"(bytes) : "memory");
}
__device__ __forceinline__ void bulk_copy_cluster(uint32_t dst, uint32_t src,
                                                  uint32_t bytes, uint32_t mbar) {
    asm volatile(
        "cp.async.bulk.shared::cluster.shared::cta.mbarrier::complete_tx::bytes "
        "[%0], [%1], %2, [%3];"
        :: "r"(dst), "r"(src), "r"(bytes), "r"(mbar) : "memory");
}
__device__ __forceinline__ void st_async_b32(uint32_t daddr, float v, uint32_t mbar) {
    asm volatile("st.async.shared::cluster.mbarrier::complete_tx::bytes.b32 [%0], %1, [%2];"
                 :: "r"(daddr), "f"(v), "r"(mbar) : "memory");
}
__device__ __forceinline__ void mbar_wait_cluster(uint32_t mbar, uint32_t par) {
    uint32_t done;
    asm volatile(
        "{\n\t"
        ".reg .pred p;\n\t"
        "mbarrier.try_wait.parity.acquire.cluster.shared::cta.b64 p, [%1], %2;\n\t"
        "selp.b32 %0, 1, 0, p;\n\t"
        "}"
        : "=r"(done) : "r"(mbar), "r"(par) : "memory");
    if (!done) {
        asm volatile(
            "{\n\t"
            ".reg .pred P1;\n\t"
            "WL_%=:\n\t"
            "mbarrier.try_wait.parity.acquire.cluster.shared::cta.b64 P1, [%0], %1, 0x989680;\n\t"
            "@P1 bra.uni WD_%=;\n\t"
            "bra.uni WL_%=;\n\t"
            "WD_%=:\n\t"
            "}"
            :: "r"(mbar), "r"(par) : "memory");
    }
}
__device__ __forceinline__ void cluster_arrive_() {
    asm volatile("barrier.cluster.arrive.aligned;" ::: "memory");
}
__device__ __forceinline__ void cluster_wait_() {
    asm volatile("barrier.cluster.wait.aligned;" ::: "memory");
}

// One weight value against 4 batches (2 f32x2 pairs)
#define QFMA(ar, wv, sA)                     \
    do {                                      \
        ull _w = pack2(wv);                   \
        fma2(ar##0, _w, sA.x);                \
        fma2(ar##1, _w, sA.y);                \
    } while (0)

extern "C" __global__ void __cluster_dims__(NSL, 1, 1) __launch_bounds__(THREADS, 1)
rnn_step_kernel(const float* __restrict__ u,
                const float* __restrict__ Wrec,
                const float* __restrict__ Winp,
                const float* __restrict__ Wout,
                const float* __restrict__ y_init,
                const float* __restrict__ rnoise,
                const float* __restrict__ inoise,
                float* __restrict__ states,
                float* __restrict__ outs)
{
    extern __shared__ float sm[];
    // sm: buf[ch][ph] 4x[520][4] | part [16][64][12] | stg [2][2][256] | 4 mbars
    float* part = sm + NCH * 2 * F_BUF;
    float* stg  = part + F_PART;
    const uint32_t bufbase  = smem_u32(sm);
    const uint32_t stgbase  = smem_u32(stg);
    const uint32_t mbarbase = smem_u32(stg + F_STG);

    const int tid  = threadIdx.x;
    const int ns   = blockIdx.x;     // cluster rank / n-slice
    const int bgc  = blockIdx.y;     // cluster-group 0..15
    const int n0   = ns * ROWS;
    const int lane = tid & 31;
    const int wid  = tid >> 5;       // 0..7
    const int g    = lane & 15;
    const int h    = lane >> 4;
    const int seg  = wid * 2 + h;    // 0..15
    const int kb   = wid * 64 + h * 32;

    const int r0 = 2 * g, r1 = 2 * g + 1, r2 = 2 * g + 32, r3 = 2 * g + 33;

    int b0c[NCH];
    #pragma unroll
    for (int c = 0; c < NCH; ++c) b0c[c] = (bgc * NCH + c) * BG;

    // ---- peer addresses ----
    uint32_t pbuf[NSL], pmbar[NSL];
    #pragma unroll
    for (int r = 0; r < NSL; ++r) {
        pbuf[r]  = mapa_rank(bufbase, r);
        pmbar[r] = mapa_rank(mbarbase, r);
    }
    const uint32_t pbuf_self  = mapa_rank(bufbase, ns);
    const uint32_t pmbar_self = mapa_rank(mbarbase, ns);

    // ---- W_rec slice into registers: 4 rows x 32 k = 32 float4 ----
    float4 wr0[8], wr1[8], wr2[8], wr3[8];
    {
        const float* p0 = Wrec + (size_t)(n0 + r0) * NN + kb;
        const float* p1 = Wrec + (size_t)(n0 + r1) * NN + kb;
        const float* p2 = Wrec + (size_t)(n0 + r2) * NN + kb;
        const float* p3 = Wrec + (size_t)(n0 + r3) * NN + kb;
        #pragma unroll
        for (int q = 0; q < 8; ++q) {
            wr0[q] = *(const float4*)(p0 + 4 * q);
            wr1[q] = *(const float4*)(p1 + 4 * q);
            wr2[q] = *(const float4*)(p2 + 4 * q);
            wr3[q] = *(const float4*)(p3 + 4 * q);
        }
    }
    float wi0 = 0.f, wi1 = 0.f, wi2 = 0.f, wi3 = 0.f;
    if (seg < NIN) {
        wi0 = Winp[(size_t)(n0 + r0) * NIN + seg];
        wi1 = Winp[(size_t)(n0 + r1) * NIN + seg];
        wi2 = Winp[(size_t)(n0 + r2) * NIN + seg];
        wi3 = Winp[(size_t)(n0 + r3) * NIN + seg];
    }

    // Reducer output assignment (1 output per thread)
    const int n_r = tid >> 2;             // 0..63
    const int b_r = tid & 3;
    const float woa = Wout[n0 + n_r];
    const float wob = Wout[NN + n0 + n_r];

    // x loader assignment (threads 0..23)
    const bool xload = (tid < NIN * BG);
    const int  xi = tid >> 2, xb = tid & 3;
    const uint32_t x_off = (uint32_t)((NN + xi) * BG + xb) * 4;

    // ---- mbarrier init: 4 barriers [chain][phase], count=1 ----
    if (tid == 0) {
        #pragma unroll
        for (int i = 0; i < NCH * 2; ++i)
            mbar_init(mbarbase + 8u * i, 1);
    }

    // ---- Seed both chains' buf[ch][0], x(0), states t=0, zero outs ----
    #pragma unroll
    for (int c = 0; c < NCH; ++c) {
        float* bufc0 = sm + (c * 2) * F_BUF;
        for (int idx = tid; idx < NN * BG; idx += THREADS)
            bufc0[idx] = y_init[idx >> 2];
        if (xload) {
            size_t off = (size_t)xi * TB + b0c[c] + xb;
            bufc0[(NN + xi) * BG + xb] = __ldcs(u + off) + __ldcs(inoise + off);
        }
        // states t=0 own slice: 256 values = 1/thread
        states[(size_t)(n0 + n_r) * TB + b0c[c] + b_r] = y_init[n0 + n_r];
        if (ns == 0) {
            for (int idx = tid; idx < NOUT * TS * BG; idx += THREADS) {
                int o   = idx / (TS * BG);
                int rem = idx - o * TS * BG;
                int t = rem >> 2;
                int b = rem & 3;
                outs[(size_t)o * TB + (size_t)t * NB + b0c[c] + b] = 0.f;
            }
        }
    }
    __syncthreads();
    cluster_arrive_();

    // ---- Prefetch per chain: x(1) and rnoise(0) ----
    float x_v[NCH], rn[NCH];
    #pragma unroll
    for (int c = 0; c < NCH; ++c) {
        x_v[c] = 0.f;
        if (xload) {
            size_t off = (size_t)xi * TB + (size_t)1 * NB + b0c[c] + xb;
            x_v[c] = __ldcs(u + off) + __ldcs(inoise + off);
        }
        rn[c] = __ldcs(rnoise + (size_t)(n0 + n_r) * TB + b0c[c] + b_r);
    }

    cluster_wait_();   // seeds + mbar inits + outs zero visible cluster-wide

    // ---- t = 0 outputs (both chains; same state) ----
    {
        float sv = y_init[n0 + n_r];
        float v0 = woa * sv;
        float v1 = wob * sv;
        v0 += __shfl_xor_sync(0xffffffffu, v0, 4);
        v0 += __shfl_xor_sync(0xffffffffu, v0, 8);
        v0 += __shfl_xor_sync(0xffffffffu, v0, 16);
        v1 += __shfl_xor_sync(0xffffffffu, v1, 4);
        v1 += __shfl_xor_sync(0xffffffffu, v1, 8);
        v1 += __shfl_xor_sync(0xffffffffu, v1, 16);
        if (lane < BG) {
            #pragma unroll
            for (int c = 0; c < NCH; ++c) {
                atomicAdd(outs + b0c[c] + lane, v0);
                atomicAdd(outs + TB + b0c[c] + lane, v1);
            }
        }
    }

    int ph[NCH][2] = {{0, 0}, {0, 0}};

    for (int t = 0; t < TS - 1; ++t) {
        const int cur = t & 1;
        const int p   = (t + 1) & 1;
        #pragma unroll
        for (int c = 0; c < NCH; ++c) {
            const uint32_t mcur = 8u * (c * 2 + cur);
            const uint32_t mnxt = 8u * (c * 2 + p);

            // ---- 1. wait chain c state t (hidden under other chain's work) ----
            if (t > 0) {
                mbar_wait_cluster(mbarbase + mcur, ph[c][cur]);
                ph[c][cur] ^= 1;
            }
            if (tid == 0 && t < TS - 2)
                mbar_expect_tx(mbarbase + mnxt, TXB);

            const float* sb = sm + (c * 2 + cur) * F_BUF;
            const float* sp = sb + kb * BG;
            const float* sextp = sb + (NN + seg) * BG;

            // ---- 2. GEMM partials: 32 k x 4 rows x 4 batches ----
            ull a00 = 0, a01 = 0;
            ull a10 = 0, a11 = 0;
            ull a20 = 0, a21 = 0;
            ull a30 = 0, a31 = 0;
            {
                #pragma unroll
                for (int q = 0; q < 8; ++q) {
                    float4 w0q = wr0[q], w1q = wr1[q], w2q = wr2[q], w3q = wr3[q];
                    #pragma unroll
                    for (int cc = 0; cc < 4; ++cc) {
                        ulonglong2 sA = *(const ulonglong2*)(sp);   // b0..b3
                        float w0v = (cc == 0) ? w0q.x : (cc == 1) ? w0q.y : (cc == 2) ? w0q.z : w0q.w;
                        float w1v = (cc == 0) ? w1q.x : (cc == 1) ? w1q.y : (cc == 2) ? w1q.z : w1q.w;
                        float w2v = (cc == 0) ? w2q.x : (cc == 1) ? w2q.y : (cc == 2) ? w2q.z : w2q.w;
                        float w3v = (cc == 0) ? w3q.x : (cc == 1) ? w3q.y : (cc == 2) ? w3q.z : w3q.w;
                        QFMA(a0, w0v, sA);
                        QFMA(a1, w1v, sA);
                        QFMA(a2, w2v, sA);
                        QFMA(a3, w3v, sA);
                        sp += BG;
                    }
                }
                if (seg < NIN) {
                    ulonglong2 sA = *(const ulonglong2*)(sextp);
                    QFMA(a0, wi0, sA);
                    QFMA(a1, wi1, sA);
                    QFMA(a2, wi2, sA);
                    QFMA(a3, wi3, sA);
                }
            }
            // ---- 3. store partials: 1 STS.128 per row ----
            {
                float4 q;
                float* pb = part + (seg * ROWS) * BP;
                unpack2(a00, q.x, q.y); unpack2(a01, q.z, q.w);
                *(float4*)(pb + r0 * BP) = q;
                unpack2(a10, q.x, q.y); unpack2(a11, q.z, q.w);
                *(float4*)(pb + r1 * BP) = q;
                unpack2(a20, q.x, q.y); unpack2(a21, q.z, q.w);
                *(float4*)(pb + r2 * BP) = q;
                unpack2(a30, q.x, q.y); unpack2(a31, q.z, q.w);
                *(float4*)(pb + r3 * BP) = q;
            }
            __syncthreads();   // partials ready (also separates chains' use of part)

            // ---- 4. reduce, tanh, update -> staging[c][p] (1 out/thread) ----
            float nsv;
            {
                float pre = 0.f;
                #pragma unroll
                for (int s_ = 0; s_ < NSEG; ++s_)
                    pre += part[(s_ * ROWS + n_r) * BP + b_r];
                float s0 = sb[(n0 + n_r) * BG + b_r];
                nsv = 0.9f * s0 + 0.1f * (tanh_fast(pre) + rn[c]);
                stg[(c * 2 + p) * SLICE + tid] = nsv;   // tid == n_r*BG + b_r
            }
            // x(t+1) push; safe after wait-t (all step-(t-1) readers of the
            // target phase finished cluster-wide before mbar-t fired).
            if (xload && t < TS - 2)
                st_async_b32(pbuf_self + (uint32_t)(c * 2 + p) * BUF_BYTES + x_off,
                             x_v[c], pmbar_self + mnxt);
            __syncthreads();   // staging slice complete

            // ---- 5. bulk push: ONE 1KB copy per rank, tx-counted ----
            // stg[c][p] reuse safety: next overwrite at step t+2; our
            // wait-(t+2) transitively requires this copy's completion.
            if (tid == 0 && t < TS - 2) {
                uint32_t src  = stgbase + (uint32_t)(c * 2 + p) * SLICE_BYTES;
                uint32_t doff = (uint32_t)(c * 2 + p) * BUF_BYTES
                              + (uint32_t)(n0 * BG) * 4;
                #pragma unroll
                for (int r = 0; r < NSL; ++r)
                    bulk_copy_cluster(pbuf[r] + doff, src, SLICE_BYTES,
                                      pmbar[r] + mnxt);
            }

            // ---- 6. off-chain: states STG, outs RED, next prefetches ----
            {
                states[(size_t)(n0 + n_r) * TB + (size_t)(t + 1) * NB
                       + b0c[c] + b_r] = nsv;

                float v0 = woa * nsv;
                float v1 = wob * nsv;
                v0 += __shfl_xor_sync(0xffffffffu, v0, 4);
                v0 += __shfl_xor_sync(0xffffffffu, v0, 8);
                v0 += __shfl_xor_sync(0xffffffffu, v0, 16);
                v1 += __shfl_xor_sync(0xffffffffu, v1, 4);
                v1 += __shfl_xor_sync(0xffffffffu, v1, 8);
                v1 += __shfl_xor_sync(0xffffffffu, v1, 16);
                if (lane < BG) {
                    size_t oc = (size_t)(t + 1) * NB + b0c[c] + lane;
                    atomicAdd(outs + oc, v0);
                    atomicAdd(outs + TB + oc, v1);
                }
            }
            if (t + 1 < TS - 1)
                rn[c] = __ldcs(rnoise + (size_t)(n0 + n_r) * TB
                               + (size_t)(t + 1) * NB + b0c[c] + b_r);
            if (xload && t + 2 <= TS - 2) {
                size_t off = (size_t)xi * TB + (size_t)(t + 2) * NB + b0c[c] + xb;
                x_v[c] = __ldcs(u + off) + __ldcs(inoise + off);
            }
        }
    }

    // keep cluster SMEM alive until all peers drained
    cluster_arrive_();
    cluster_wait_();
}

extern "C" void kernel_launch(void* const* d_in, const int* in_sizes, int n_in,
                              void* d_out, int out_size)
{
    const float* u      = (const float*)d_in[0];
    const float* Wrec   = (const float*)d_in[1];
    const float* Winp   = (const float*)d_in[2];
    const float* Wout   = (const float*)d_in[3];
    const float* y_init = (const float*)d_in[4];
    const float* rnoise = (const float*)d_in[5];
    const float* inoise = (const float*)d_in[6];

    float* states = (float*)d_out;
    float* outs   = states + (size_t)NN * TB;

    cudaFuncSetAttribute(rnn_step_kernel,
                         cudaFuncAttributeMaxDynamicSharedMemorySize, SMEM_BYTES);

    dim3 grid(NSL, 16, 1);   // 8 x 16 = 128 CTAs
    rnn_step_kernel<<<grid, THREADS, SMEM_BYTES>>>(u, Wrec, Winp, Wout, y_init,
                                                   rnoise, inoise, states, outs);
}

// round 16
// speedup vs baseline: 1.2095x; 1.2095x over previous
#include <cuda_runtime.h>
#include <cstdint>

// Problem constants
#define NN   512
#define NIN  6
#define NOUT 2
#define TS   1200
#define NB   128
#define TB   (TS * NB)          // 153600

// Decomposition: 8 cluster-groups x (cluster of 8 n-slice CTAs) = 64 CTAs.
// Each cluster interleaves TWO independent 8-batch chains (A/B); 512 threads
// (16 warps) halve the per-chain compute C on the T = C + L critical path.
#define NSL     8               // n-slices (cluster size)
#define ROWS    64              // rows of W_rec per CTA
#define NCH     2               // chains per cluster
#define BG      8               // batch per group (16 groups total)
#define THREADS 512             // 16 warps -> FFMA2 floor 1024 cyc
#define NSEG    16              // k-segments (one per warp, 32 k each)
#define BP      12              // partials row pad (floats, mult of 4)

#define F_BUF   ((NN + NIN + 2) * BG)   // 4160 floats per state buffer
#define BUF_BYTES (F_BUF * 4)           // 16640
#define F_PART  (NSEG * ROWS * BP)      // 12288
#define SLICE   (ROWS * BG)             // 512 floats
#define SLICE_BYTES (SLICE * 4)         // 2048
#define F_STG   (NCH * 2 * SLICE)       // 2048
#define F_MBAR  8                       // 4 x 8-byte mbarriers
#define SMEM_FLOATS (NCH * 2 * F_BUF + F_PART + F_STG + F_MBAR)
#define SMEM_BYTES  (SMEM_FLOATS * 4)   // 123,936 B

// tx bytes per chain-phase: 8 bulk copies x 2048 B + 48 x 4 B (x rows)
#define TXB (NSL * SLICE_BYTES + NIN * BG * 4)   // 16576

typedef unsigned long long ull;

__device__ __forceinline__ ull pack2(float x) {
    ull r;
    unsigned int v = __float_as_uint(x);
    asm("mov.b64 %0, {%1, %1};" : "=l"(r) : "r"(v));
    return r;
}
__device__ __forceinline__ void fma2(ull& d, ull a, ull b) {
    asm("fma.rn.f32x2 %0, %1, %2, %0;" : "+l"(d) : "l"(a), "l"(b));
}
__device__ __forceinline__ void unpack2(ull v, float& lo, float& hi) {
    unsigned int l, h;
    asm("mov.b64 {%0, %1}, %2;" : "=r"(l), "=r"(h) : "l"(v));
    lo = __uint_as_float(l);
    hi = __uint_as_float(h);
}
__device__ __forceinline__ float tanh_fast(float x) {
    float r;
    asm("tanh.approx.f32 %0, %1;" : "=f"(r) : "f"(x));
    return r;
}
__device__ __forceinline__ uint32_t smem_u32(const void* p) {
    uint32_t a;
    asm("{ .reg .u64 t; cvta.to.shared.u64 t, %1; cvt.u32.u64 %0, t; }"
        : "=r"(a) : "l"(p));
    return a;
}
__device__ __forceinline__ uint32_t mapa_rank(uint32_t addr, uint32_t rank) {
    uint32_t r;
    asm("mapa.shared::cluster.u32 %0, %1, %2;" : "=r"(r) : "r"(addr), "r"(rank));
    return r;
}
__device__ __forceinline__ void mbar_init(uint32_t addr, uint32_t cnt) {
    asm volatile("mbarrier.init.shared.b64 [%0], %1;" :: "r"(addr), "r"(cnt) : "memory");
}
__device__ __forceinline__ void mbar_expect_tx(uint32_t addr, uint32_t bytes) {
    asm volatile("mbarrier.arrive.expect_tx.shared.b64 _, [%0], %1;"
                 :: "r"(addr), "r"(bytes) : "memory");
}
__device__ __forceinline__ void bulk_copy_cluster(uint32_t dst, uint32_t src,
                                                  uint32_t bytes, uint32_t mbar) {
    asm volatile(
        "cp.async.bulk.shared::cluster.shared::cta.mbarrier::complete_tx::bytes "
        "[%0], [%1], %2, [%3];"
        :: "r"(dst), "r"(src), "r"(bytes), "r"(mbar) : "memory");
}
__device__ __forceinline__ void st_async_b32(uint32_t daddr, float v, uint32_t mbar) {
    asm volatile("st.async.shared::cluster.mbarrier::complete_tx::bytes.b32 [%0], %1, [%2];"
                 :: "r"(daddr), "f"(v), "r"(mbar) : "memory");
}
__device__ __forceinline__ void mbar_wait_cluster(uint32_t mbar, uint32_t par) {
    uint32_t done;
    asm volatile(
        "{\n\t"
        ".reg .pred p;\n\t"
        "mbarrier.try_wait.parity.acquire.cluster.shared::cta.b64 p, [%1], %2;\n\t"
        "selp.b32 %0, 1, 0, p;\n\t"
        "}"
        : "=r"(done) : "r"(mbar), "r"(par) : "memory");
    if (!done) {
        asm volatile(
            "{\n\t"
            ".reg .pred P1;\n\t"
            "WL_%=:\n\t"
            "mbarrier.try_wait.parity.acquire.cluster.shared::cta.b64 P1, [%0], %1, 0x989680;\n\t"
            "@P1 bra.uni WD_%=;\n\t"
            "bra.uni WL_%=;\n\t"
            "WD_%=:\n\t"
            "}"
            :: "r"(mbar), "r"(par) : "memory");
    }
}
__device__ __forceinline__ void cluster_arrive_() {
    asm volatile("barrier.cluster.arrive.aligned;" ::: "memory");
}
__device__ __forceinline__ void cluster_wait_() {
    asm volatile("barrier.cluster.wait.aligned;" ::: "memory");
}

// One weight value against 8 batches (4 f32x2 pairs)
#define QFMA(ar, wv, sA, sB)                 \
    do {                                      \
        ull _w = pack2(wv);                   \
        fma2(ar##0, _w, sA.x);                \
        fma2(ar##1, _w, sA.y);                \
        fma2(ar##2, _w, sB.x);                \
        fma2(ar##3, _w, sB.y);                \
    } while (0)

extern "C" __global__ void __cluster_dims__(NSL, 1, 1) __launch_bounds__(THREADS, 1)
rnn_step_kernel(const float* __restrict__ u,
                const float* __restrict__ Wrec,
                const float* __restrict__ Winp,
                const float* __restrict__ Wout,
                const float* __restrict__ y_init,
                const float* __restrict__ rnoise,
                const float* __restrict__ inoise,
                float* __restrict__ states,
                float* __restrict__ outs)
{
    extern __shared__ float sm[];
    // sm: buf[ch][ph] 4x[520][8] | part [16][64][12] | stg [2][2][512] | 4 mbars
    float* part = sm + NCH * 2 * F_BUF;
    float* stg  = part + F_PART;
    const uint32_t bufbase  = smem_u32(sm);
    const uint32_t stgbase  = smem_u32(stg);
    const uint32_t mbarbase = smem_u32(stg + F_STG);

    const int tid  = threadIdx.x;
    const int ns   = blockIdx.x;     // cluster rank / n-slice
    const int bgc  = blockIdx.y;     // cluster-group 0..7
    const int n0   = ns * ROWS;
    const int lane = tid & 31;
    const int wid  = tid >> 5;       // 0..15 = k-segment (32 k's each)
    const int kb   = wid * 32;

    const int r0 = lane;             // local rows: lane, lane+32
    const int r1 = lane + 32;

    int b0c[NCH];
    #pragma unroll
    for (int c = 0; c < NCH; ++c) b0c[c] = (bgc * NCH + c) * BG;

    // ---- peer addresses ----
    uint32_t pbuf[NSL], pmbar[NSL];
    #pragma unroll
    for (int r = 0; r < NSL; ++r) {
        pbuf[r]  = mapa_rank(bufbase, r);
        pmbar[r] = mapa_rank(mbarbase, r);
    }
    const uint32_t pbuf_self  = mapa_rank(bufbase, ns);
    const uint32_t pmbar_self = mapa_rank(mbarbase, ns);

    // ---- W_rec slice into registers: 2 rows x 32 k = 16 float4 ----
    float4 wr0[8], wr1[8];
    {
        const float* p0 = Wrec + (size_t)(n0 + r0) * NN + kb;
        const float* p1 = Wrec + (size_t)(n0 + r1) * NN + kb;
        #pragma unroll
        for (int q = 0; q < 8; ++q) {
            wr0[q] = *(const float4*)(p0 + 4 * q);
            wr1[q] = *(const float4*)(p1 + 4 * q);
        }
    }
    // Input-term weights (k-row 512+wid), only warps 0..5 active
    float wi0 = 0.f, wi1 = 0.f;
    if (wid < NIN) {
        wi0 = Winp[(size_t)(n0 + r0) * NIN + wid];
        wi1 = Winp[(size_t)(n0 + r1) * NIN + wid];
    }

    // Reducer output assignment (1 output per thread)
    const int n_r = tid >> 3;             // 0..63
    const int b_r = tid & 7;
    const float woa = Wout[n0 + n_r];
    const float wob = Wout[NN + n0 + n_r];

    // x loader assignment (threads 0..47)
    const bool xload = (tid < NIN * BG);
    const int  xi = tid >> 3, xb = tid & 7;
    const uint32_t x_off = (uint32_t)((NN + xi) * BG + xb) * 4;

    // ---- mbarrier init: 4 barriers [chain][phase], count=1 ----
    if (tid == 0) {
        #pragma unroll
        for (int i = 0; i < NCH * 2; ++i)
            mbar_init(mbarbase + 8u * i, 1);
    }

    // ---- Seed both chains' buf[ch][0], x(0), states t=0, zero outs ----
    #pragma unroll
    for (int c = 0; c < NCH; ++c) {
        float* bufc0 = sm + (c * 2) * F_BUF;
        for (int idx = tid; idx < NN * BG; idx += THREADS)
            bufc0[idx] = y_init[idx >> 3];
        if (xload) {
            size_t off = (size_t)xi * TB + b0c[c] + xb;
            bufc0[(NN + xi) * BG + xb] = __ldcs(u + off) + __ldcs(inoise + off);
        }
        // states t=0 own slice: 512 values = 1/thread
        states[(size_t)(n0 + n_r) * TB + b0c[c] + b_r] = y_init[n0 + n_r];
        if (ns == 0) {
            for (int idx = tid; idx < NOUT * TS * BG; idx += THREADS) {
                int o   = idx / (TS * BG);
                int rem = idx - o * TS * BG;
                int t = rem >> 3;
                int b = rem & 7;
                outs[(size_t)o * TB + (size_t)t * NB + b0c[c] + b] = 0.f;
            }
        }
    }
    __syncthreads();
    cluster_arrive_();

    // ---- Prefetch per chain: x(1) and rnoise(0) ----
    float x_v[NCH], rn[NCH];
    #pragma unroll
    for (int c = 0; c < NCH; ++c) {
        x_v[c] = 0.f;
        if (xload) {
            size_t off = (size_t)xi * TB + (size_t)1 * NB + b0c[c] + xb;
            x_v[c] = __ldcs(u + off) + __ldcs(inoise + off);
        }
        rn[c] = __ldcs(rnoise + (size_t)(n0 + n_r) * TB + b0c[c] + b_r);
    }

    cluster_wait_();   // seeds + mbar inits + outs zero visible cluster-wide

    // ---- t = 0 outputs (both chains; same state) ----
    {
        float sv = y_init[n0 + n_r];
        float v0 = woa * sv;
        float v1 = wob * sv;
        v0 += __shfl_xor_sync(0xffffffffu, v0, 8);
        v0 += __shfl_xor_sync(0xffffffffu, v0, 16);
        v1 += __shfl_xor_sync(0xffffffffu, v1, 8);
        v1 += __shfl_xor_sync(0xffffffffu, v1, 16);
        if (lane < BG) {
            #pragma unroll
            for (int c = 0; c < NCH; ++c) {
                atomicAdd(outs + b0c[c] + lane, v0);
                atomicAdd(outs + TB + b0c[c] + lane, v1);
            }
        }
    }

    int ph[NCH][2] = {{0, 0}, {0, 0}};

    for (int t = 0; t < TS - 1; ++t) {
        const int cur = t & 1;
        const int p   = (t + 1) & 1;
        #pragma unroll
        for (int c = 0; c < NCH; ++c) {
            const uint32_t mcur = 8u * (c * 2 + cur);
            const uint32_t mnxt = 8u * (c * 2 + p);

            // ---- 1. wait chain c state t (hidden under other chain's work) ----
            if (t > 0) {
                mbar_wait_cluster(mbarbase + mcur, ph[c][cur]);
                ph[c][cur] ^= 1;
            }
            if (tid == 0 && t < TS - 2)
                mbar_expect_tx(mbarbase + mnxt, TXB);

            const float* sb = sm + (c * 2 + cur) * F_BUF;
            const float* sp = sb + kb * BG;
            const float* sextp = sb + (NN + wid) * BG;

            // ---- 2. GEMM partials: 32 k x 2 rows x 8 batches ----
            ull a00 = 0, a01 = 0, a02 = 0, a03 = 0;   // row lane
            ull a10 = 0, a11 = 0, a12 = 0, a13 = 0;   // row lane+32
            {
                #pragma unroll
                for (int q = 0; q < 8; ++q) {
                    float4 w0q = wr0[q], w1q = wr1[q];
                    #pragma unroll
                    for (int cc = 0; cc < 4; ++cc) {
                        ulonglong2 sA = *(const ulonglong2*)(sp);      // b0..b3
                        ulonglong2 sB = *(const ulonglong2*)(sp + 4);  // b4..b7
                        float w0v = (cc == 0) ? w0q.x : (cc == 1) ? w0q.y : (cc == 2) ? w0q.z : w0q.w;
                        float w1v = (cc == 0) ? w1q.x : (cc == 1) ? w1q.y : (cc == 2) ? w1q.z : w1q.w;
                        QFMA(a0, w0v, sA, sB);
                        QFMA(a1, w1v, sA, sB);
                        sp += BG;
                    }
                }
                if (wid < NIN) {
                    ulonglong2 sA = *(const ulonglong2*)(sextp);
                    ulonglong2 sB = *(const ulonglong2*)(sextp + 4);
                    QFMA(a0, wi0, sA, sB);
                    QFMA(a1, wi1, sA, sB);
                }
            }
            // ---- 3. store partials: per row, 8 floats as 2x STS.128 ----
            {
                float4 q;
                float* pb = part + (wid * ROWS) * BP;
                unpack2(a00, q.x, q.y); unpack2(a01, q.z, q.w);
                *(float4*)(pb + r0 * BP) = q;
                unpack2(a02, q.x, q.y); unpack2(a03, q.z, q.w);
                *(float4*)(pb + r0 * BP + 4) = q;
                unpack2(a10, q.x, q.y); unpack2(a11, q.z, q.w);
                *(float4*)(pb + r1 * BP) = q;
                unpack2(a12, q.x, q.y); unpack2(a13, q.z, q.w);
                *(float4*)(pb + r1 * BP + 4) = q;
            }
            __syncthreads();   // partials ready (also separates chains' use of part)

            // ---- 4. reduce, tanh, update -> staging[c][p] (1 out/thread) ----
            float nsv;
            {
                float pre = 0.f;
                #pragma unroll
                for (int s_ = 0; s_ < NSEG; ++s_)
                    pre += part[(s_ * ROWS + n_r) * BP + b_r];
                float s0 = sb[(n0 + n_r) * BG + b_r];
                nsv = 0.9f * s0 + 0.1f * (tanh_fast(pre) + rn[c]);
                stg[(c * 2 + p) * SLICE + tid] = nsv;   // tid == n_r*BG + b_r
            }
            // x(t+1) push; safe after wait-t (all step-(t-1) readers of the
            // target phase finished cluster-wide before mbar-t fired).
            if (xload && t < TS - 2)
                st_async_b32(pbuf_self + (uint32_t)(c * 2 + p) * BUF_BYTES + x_off,
                             x_v[c], pmbar_self + mnxt);
            __syncthreads();   // staging slice complete

            // ---- 5. bulk push: ONE 2KB copy per rank, tx-counted ----
            // stg[c][p] reuse safety: next overwrite at step t+2; our
            // wait-(t+2) transitively requires this copy's completion.
            if (tid == 0 && t < TS - 2) {
                uint32_t src  = stgbase + (uint32_t)(c * 2 + p) * SLICE_BYTES;
                uint32_t doff = (uint32_t)(c * 2 + p) * BUF_BYTES
                              + (uint32_t)(n0 * BG) * 4;
                #pragma unroll
                for (int r = 0; r < NSL; ++r)
                    bulk_copy_cluster(pbuf[r] + doff, src, SLICE_BYTES,
                                      pmbar[r] + mnxt);
            }

            // ---- 6. off-chain: states STG, outs RED, next prefetches ----
            {
                states[(size_t)(n0 + n_r) * TB + (size_t)(t + 1) * NB
                       + b0c[c] + b_r] = nsv;

                float v0 = woa * nsv;
                float v1 = wob * nsv;
                v0 += __shfl_xor_sync(0xffffffffu, v0, 8);
                v0 += __shfl_xor_sync(0xffffffffu, v0, 16);
                v1 += __shfl_xor_sync(0xffffffffu, v1, 8);
                v1 += __shfl_xor_sync(0xffffffffu, v1, 16);
                if (lane < BG) {
                    size_t oc = (size_t)(t + 1) * NB + b0c[c] + lane;
                    atomicAdd(outs + oc, v0);
                    atomicAdd(outs + TB + oc, v1);
                }
            }
            if (t + 1 < TS - 1)
                rn[c] = __ldcs(rnoise + (size_t)(n0 + n_r) * TB
                               + (size_t)(t + 1) * NB + b0c[c] + b_r);
            if (xload && t + 2 <= TS - 2) {
                size_t off = (size_t)xi * TB + (size_t)(t + 2) * NB + b0c[c] + xb;
                x_v[c] = __ldcs(u + off) + __ldcs(inoise + off);
            }
        }
    }

    // keep cluster SMEM alive until all peers drained
    cluster_arrive_();
    cluster_wait_();
}

extern "C" void kernel_launch(void* const* d_in, const int* in_sizes, int n_in,
                              void* d_out, int out_size)
{
    const float* u      = (const float*)d_in[0];
    const float* Wrec   = (const float*)d_in[1];
    const float* Winp   = (const float*)d_in[2];
    const float* Wout   = (const float*)d_in[3];
    const float* y_init = (const float*)d_in[4];
    const float* rnoise = (const float*)d_in[5];
    const float* inoise = (const float*)d_in[6];

    float* states = (float*)d_out;
    float* outs   = states + (size_t)NN * TB;

    cudaFuncSetAttribute(rnn_step_kernel,
                         cudaFuncAttributeMaxDynamicSharedMemorySize, SMEM_BYTES);

    dim3 grid(NSL, 8, 1);   // 8 x 8 = 64 CTAs
    rnn_step_kernel<<<grid, THREADS, SMEM_BYTES>>>(u, Wrec, Winp, Wout, y_init,
                                                   rnoise, inoise, states, outs);
}